// round 8
// baseline (speedup 1.0000x reference)
#include <cuda_runtime.h>
#include <cuda_fp16.h>
#include <math.h>
#include <stdint.h>

// ---------------- problem constants ----------------
constexpr int B    = 2;
constexpr int CIN  = 192;
constexpr int CMID = 180;
constexpr int Hh   = 96;
constexpr int Ww   = 96;
constexpr int HW   = Hh * Ww;          // 9216
constexpr int KK   = 9;
constexpr int G    = 10;
constexpr int CG   = CMID / G;         // 18
constexpr int KDIM = CMID * KK;        // 1620
constexpr int KDIM_P = 1632;           // 51 chunks of 32

constexpr size_t FSTR  = (size_t)192 * HW;     // fp16/f32 feature stride
constexpr size_t OSTR  = (size_t)360 * HW;     // offs stride
constexpr size_t CSTR  = (size_t)KDIM_P * HW;  // col plane stride
constexpr size_t XTSTR = (size_t)HW * 240;     // pixel-major xr: [p][g*24+c]

// ---------------- device scratch (zero-initialized statics) ----------------
__device__ __align__(256) float g_offs[(size_t)B * OSTR];
__device__ __align__(256) float g_fw  [(size_t)B * FSTR];
__device__ __align__(256) float g_fh  [(size_t)B * FSTR];
__device__ float g_avg [B * CMID];
__device__ float g_attn[B * 2];
// fp16 activation planes (pad rows stay zero forever)
__device__ __align__(256) __half g_xp  [(size_t)B * 192 * HW];
__device__ __align__(256) __half g_xrp [(size_t)B * FSTR];
__device__ __align__(256) __half g_xrt [(size_t)B * XTSTR];
__device__ __align__(256) __half g_cw  [(size_t)B * CSTR];
__device__ __align__(256) __half g_ch  [(size_t)B * CSTR];
// prepacked weights: [plane(hi,lo)][Kpad][Mpad] k-major (lo plane unused 1-pass)
__device__ __align__(256) __half g_wpR[2 * 192  * 192];
__device__ __align__(256) __half g_wpO[2 * 192  * 384];
__device__ __align__(256) __half g_wpW[2 * 1632 * 192];
__device__ __align__(256) __half g_wpH[2 * 1632 * 192];
__device__ __align__(256) __half g_wpE[2 * 192  * 192];

// ---------------- PTX helpers (arch-generic) ----------------
__device__ __forceinline__ uint32_t smem_to_u32(const void* p) {
    uint32_t a;
    asm("{ .reg .u64 t; cvta.to.shared.u64 t, %1; cvt.u32.u64 %0, t; }"
        : "=r"(a) : "l"(p));
    return a;
}
__device__ __forceinline__ void cp16(uint32_t dst, const void* src) {
    asm volatile("cp.async.cg.shared.global [%0], [%1], 16;" :: "r"(dst), "l"(src));
}
#define CP_COMMIT() asm volatile("cp.async.commit_group;" ::: "memory")
#define CP_WAIT(n)  asm volatile("cp.async.wait_group %0;" :: "n"(n) : "memory")

__device__ __forceinline__ void ldsm_x4_t(uint32_t* r, uint32_t addr) {
    asm volatile("ldmatrix.sync.aligned.m8n8.x4.trans.shared.b16 {%0,%1,%2,%3}, [%4];"
        : "=r"(r[0]), "=r"(r[1]), "=r"(r[2]), "=r"(r[3]) : "r"(addr));
}
__device__ __forceinline__ void mma16816(float* d, const uint32_t* a, const uint32_t* b) {
    asm volatile("mma.sync.aligned.m16n8k16.row.col.f32.f16.f16.f32 "
        "{%0,%1,%2,%3}, {%4,%5,%6,%7}, {%8,%9}, {%0,%1,%2,%3};"
        : "+f"(d[0]), "+f"(d[1]), "+f"(d[2]), "+f"(d[3])
        : "r"(a[0]), "r"(a[1]), "r"(a[2]), "r"(a[3]), "r"(b[0]), "r"(b[1]));
}

// ---------------- tensor GEMM (fp16; PASSES=2 adds weight-lo correction) ----
// C[z][m][p] = sum_k W[m][k] * Act[z][k][p] + bias[m]
// grid = (72, Mpad/192, B), block = 256 (8 warps: 4m x 2n of 48x64 tiles)
template <int PASSES, bool WF, bool PLANES, bool MIX, bool ACCMEAN>
__global__ void __launch_bounds__(256, 1)
tgemm_kernel(const __half* __restrict__ actp, size_t strideAct,
             const float* __restrict__ mA, const float* __restrict__ mB,
             const float* __restrict__ attnp,
             const __half* __restrict__ Wp, int nChunks,
             const float* __restrict__ bias, int Mvalid,
             float* __restrict__ outF, size_t strideOF,
             __half* __restrict__ outP, size_t strideOP,
             float* __restrict__ avgp)
{
    constexpr int A_BUF = PASSES * 12800;
    constexpr int SMB_B = 2 * A_BUF;
    extern __shared__ char smem[];
    const uint32_t sb = smem_to_u32(smem);
    const int tid = threadIdx.x, lane = tid & 31, wid = tid >> 5;
    const int wm = wid & 3, wn = wid >> 2;
    const int z = blockIdx.z, yb = blockIdx.y;
    const int pbase = blockIdx.x * 128;
    const int Mpad = gridDim.y * 192;
    const size_t wPlane = (size_t)nChunks * 32 * Mpad;

    const __half* actz = MIX ? nullptr : (actp + (size_t)z * strideAct + pbase);
    const float* mAz = MIX ? (mA + (size_t)z * strideAct + pbase) : nullptr;
    const float* mBz = MIX ? (mB + (size_t)z * strideAct + pbase) : nullptr;
    float c0 = 0.f, c1 = 0.f;
    if (MIX) { c0 = attnp[z * 2]; c1 = attnp[z * 2 + 1]; }

    auto loadChunk = [&](int kc, int s) {
#pragma unroll
        for (int i = 0; i < 3 * PASSES; i++) {
            int c = tid + i * 256;
            int pl = c / 768, rem = c % 768, row = rem / 24, cc = rem % 24;
            uint32_t dst = sb + s * A_BUF + pl * 12800 + row * 400 + cc * 16;
            const __half* src = Wp + (size_t)pl * wPlane
                + (size_t)(kc * 32 + row) * Mpad + yb * 192 + cc * 8;
            cp16(dst, src);
        }
#pragma unroll
        for (int i = 0; i < 2; i++) {
            int c = tid + i * 256;
            int row = c >> 4, cc = c & 15;
            uint32_t dst = sb + SMB_B + s * 8704 + row * 272 + cc * 16;
            if (!MIX) {
                cp16(dst, actz + (size_t)(kc * 32 + row) * HW + cc * 8);
            } else {
                size_t off = (size_t)(kc * 32 + row) * HW + cc * 8;
                float4 a0 = *reinterpret_cast<const float4*>(mAz + off);
                float4 a1 = *reinterpret_cast<const float4*>(mAz + off + 4);
                float4 b0 = *reinterpret_cast<const float4*>(mBz + off);
                float4 b1 = *reinterpret_cast<const float4*>(mBz + off + 4);
                __half2 h0 = __floats2half2_rn(c0 * a0.x + c1 * b0.x, c0 * a0.y + c1 * b0.y);
                __half2 h1 = __floats2half2_rn(c0 * a0.z + c1 * b0.z, c0 * a0.w + c1 * b0.w);
                __half2 h2 = __floats2half2_rn(c0 * a1.x + c1 * b1.x, c0 * a1.y + c1 * b1.y);
                __half2 h3 = __floats2half2_rn(c0 * a1.z + c1 * b1.z, c0 * a1.w + c1 * b1.w);
                asm volatile("st.shared.v4.b32 [%0], {%1, %2, %3, %4};"
                    :: "r"(dst),
                       "r"(*reinterpret_cast<uint32_t*>(&h0)),
                       "r"(*reinterpret_cast<uint32_t*>(&h1)),
                       "r"(*reinterpret_cast<uint32_t*>(&h2)),
                       "r"(*reinterpret_cast<uint32_t*>(&h3)) : "memory");
            }
        }
    };

    const uint32_t aRow  = ((lane >> 4) & 1) * 8 + (lane & 7);
    const uint32_t aColB = (uint32_t)(wm * 48 + ((lane >> 3) & 1) * 8) * 2;
    const uint32_t bRow  = ((lane >> 3) & 1) * 8 + (lane & 7);
    const uint32_t bColB = (uint32_t)(wn * 64 + ((lane >> 4) & 1) * 8) * 2;
    const uint32_t aAddr = sb + aRow * 400 + aColB;
    const uint32_t bAddr = sb + SMB_B + bRow * 272 + bColB;

    float acc[3][8][4];
#pragma unroll
    for (int i = 0; i < 3; i++)
#pragma unroll
        for (int j = 0; j < 8; j++)
#pragma unroll
            for (int q = 0; q < 4; q++) acc[i][j][q] = 0.f;

    loadChunk(0, 0);
    CP_COMMIT();

    for (int t = 0; t < nChunks; t++) {
        const int s = t & 1;
        if (t + 1 < nChunks) {
            loadChunk(t + 1, s ^ 1);
            CP_COMMIT();
            CP_WAIT(1);
        } else {
            CP_WAIT(0);
        }
        __syncthreads();

        const uint32_t aB = s * A_BUF, bB = s * 8704;
#pragma unroll
        for (int ks = 0; ks < 2; ks++) {
            uint32_t Ah[3][4], Al[3][4], Bf[4][4];
#pragma unroll
            for (int mt = 0; mt < 3; mt++) {
                ldsm_x4_t(Ah[mt], aAddr + aB + mt * 32 + ks * 6400);
                if (PASSES == 2)
                    ldsm_x4_t(Al[mt], aAddr + aB + 12800 + mt * 32 + ks * 6400);
            }
#pragma unroll
            for (int ntp = 0; ntp < 4; ntp++)
                ldsm_x4_t(Bf[ntp], bAddr + bB + ntp * 32 + ks * 4352);
#pragma unroll
            for (int mt = 0; mt < 3; mt++)
#pragma unroll
                for (int nt = 0; nt < 8; nt++) {
                    const uint32_t* bp = &Bf[nt >> 1][(nt & 1) * 2];
                    mma16816(acc[mt][nt], Ah[mt], bp);
                    if (PASSES == 2)
                        mma16816(acc[mt][nt], Al[mt], bp);
                }
        }
        __syncthreads();
    }

    // epilogue
    float* oF = WF ? (outF + (size_t)z * strideOF) : nullptr;
    __half* oP = PLANES ? (outP + (size_t)z * strideOP) : nullptr;
#pragma unroll
    for (int mt = 0; mt < 3; mt++) {
#pragma unroll
        for (int half = 0; half < 2; half++) {
            const int m = yb * 192 + wm * 48 + mt * 16 + half * 8 + (lane >> 2);
            float msum = 0.f;
            if (m < Mvalid) {
                const float bv = bias[m];
#pragma unroll
                for (int nt = 0; nt < 8; nt++) {
                    const int n0 = pbase + wn * 64 + nt * 8 + (lane & 3) * 2;
                    float v0 = acc[mt][nt][half * 2 + 0] + bv;
                    float v1 = acc[mt][nt][half * 2 + 1] + bv;
                    if (WF)
                        *reinterpret_cast<float2*>(&oF[(size_t)m * HW + n0]) =
                            make_float2(v0, v1);
                    if (PLANES)
                        *reinterpret_cast<__half2*>(&oP[(size_t)m * HW + n0]) =
                            __floats2half2_rn(v0, v1);
                    if (ACCMEAN) msum += v0 + v1;
                }
            }
            if (ACCMEAN) {
                msum += __shfl_xor_sync(0xffffffffu, msum, 1);
                msum += __shfl_xor_sync(0xffffffffu, msum, 2);
                if ((lane & 3) == 0 && m < Mvalid)
                    atomicAdd(&avgp[z * CMID + m], msum);
            }
        }
    }
}

// ---------------- fused prep: weight prepacks + x->fp16 + avg zero ----------
__device__ __forceinline__ void prep_one(const float* W, int Kd, int Mvalid,
                                         int Mpad, int Kpad, __half* dst, int idx)
{
    int k = idx / Mpad, m = idx % Mpad;
    float v = (k < Kd && m < Mvalid) ? W[(size_t)m * Kd + k] : 0.f;
    __half h = __float2half_rn(v);
    __half l = __float2half_rn(v - __half2float(h));
    dst[idx] = h;
    dst[(size_t)Kpad * Mpad + idx] = l;
}

constexpr int N_R = 192 * 192;
constexpr int N_O = 192 * 384;
constexpr int N_W = 1632 * 192;
constexpr int N_E = 192 * 192;
constexpr int N_X = (B * CIN * HW) / 2;
constexpr int PREP_TOTAL = N_R + N_O + 2 * N_W + N_E + N_X;

__global__ void prep_kernel(const float* __restrict__ w_reduce,
                            const float* __restrict__ w_offset,
                            const float* __restrict__ w_dcnw,
                            const float* __restrict__ w_dcnh,
                            const float* __restrict__ w_expand,
                            const float* __restrict__ x,
                            __half* __restrict__ wpR, __half* __restrict__ wpO,
                            __half* __restrict__ wpW, __half* __restrict__ wpH,
                            __half* __restrict__ wpE, __half* __restrict__ xp,
                            float* __restrict__ avgp)
{
    int idx = blockIdx.x * blockDim.x + threadIdx.x;
    if (idx < B * CMID) avgp[idx] = 0.f;
    if (idx >= PREP_TOTAL) return;
    if (idx < N_R) { prep_one(w_reduce, 192, 180, 192, 192, wpR, idx); return; }
    idx -= N_R;
    if (idx < N_O) { prep_one(w_offset, 180, 360, 384, 192, wpO, idx); return; }
    idx -= N_O;
    if (idx < N_W) { prep_one(w_dcnw, 1620, 180, 192, 1632, wpW, idx); return; }
    idx -= N_W;
    if (idx < N_W) { prep_one(w_dcnh, 1620, 180, 192, 1632, wpH, idx); return; }
    idx -= N_W;
    if (idx < N_E) { prep_one(w_expand, 180, 192, 192, 192, wpE, idx); return; }
    idx -= N_E;
    float2 v = reinterpret_cast<const float2*>(x)[idx];
    reinterpret_cast<__half2*>(xp)[idx] = __floats2half2_rn(v.x, v.y);
}

// ---------------- transpose: xrp [c][p] fp16 -> xrt [p][g*24+c] fp16 --------
__global__ void __launch_bounds__(256)
transpose_kernel(const __half* __restrict__ xrp, __half* __restrict__ xrt)
{
    __shared__ __half sm[64][248];
    const int b = blockIdx.y;
    const int p0 = blockIdx.x * 64;
    const int tid = threadIdx.x;

    // zero (pad channels 18..23 per group must be 0)
    for (int i = tid; i < 64 * 124; i += 256)
        reinterpret_cast<uint32_t*>(&sm[0][0])[i] = 0u;
    __syncthreads();

    const __half* src = xrp + (size_t)b * FSTR;
#pragma unroll
    for (int it = 0; it < 45; it++) {
        int c = it * 4 + (tid >> 6);
        int px = tid & 63;
        __half v = src[(size_t)c * HW + p0 + px];
        sm[px][(c / 18) * 24 + (c % 18)] = v;
    }
    __syncthreads();

    __half* dst = xrt + (size_t)b * XTSTR + (size_t)p0 * 240;
    for (int i = tid; i < 64 * 30; i += 256) {
        int px = i / 30, k = i % 30;
        uint4 v = *reinterpret_cast<uint4*>(&sm[px][k * 8]);
        *reinterpret_cast<uint4*>(dst + (size_t)px * 240 + k * 8) = v;
    }
}

// ---------------- deformable im2col v3: 2 px/thread, uint4 gathers ----------
__global__ void __launch_bounds__(128)
im2col_kernel(const __half* __restrict__ xrt, const float* __restrict__ offs,
              __half* __restrict__ cw, __half* __restrict__ chh)
{
    const int b = blockIdx.z, g = blockIdx.y;
    const int pp = blockIdx.x * 128 + threadIdx.x;   // pixel pair 0..4607
    const int p0 = pp * 2;
    const int h0 = p0 / Ww, w0 = p0 % Ww;            // both px share row h0

    const __half* xb = xrt + (size_t)b * XTSTR + g * 24;

    for (int conv = 0; conv < 2; conv++) {
        const float* offb = offs + (size_t)b * OSTR
            + (size_t)((conv ? CMID : 0) + g * 18) * HW;
        __half* colb = (conv ? chh : cw) + (size_t)b * CSTR
            + (size_t)(g * CG) * KK * HW + p0;

        for (int kk = 0; kk < KK; kk++) {
            float2 oy = *reinterpret_cast<const float2*>(&offb[(size_t)(kk * 2) * HW + p0]);
            float2 ox = *reinterpret_cast<const float2*>(&offb[(size_t)(kk * 2 + 1) * HW + p0]);

            uint32_t cdw[2][4][12];
            float wgt[2][4];
#pragma unroll
            for (int px = 0; px < 2; px++) {
                float sy = (px ? oy.y : oy.x) + (float)(kk / 3 - 1 + h0);
                float sx = (px ? ox.y : ox.x) + (float)(kk % 3 - 1 + w0 + px);
                float y0f = floorf(sy), x0f = floorf(sx);
                float dy = sy - y0f, dx = sx - x0f;
                int y0 = (int)y0f, x0 = (int)x0f;
                int y1 = y0 + 1, x1 = x0 + 1;
                bool vy0 = (y0 >= 0) & (y0 < Hh);
                bool vy1 = (y1 >= 0) & (y1 < Hh);
                bool vx0 = (x0 >= 0) & (x0 < Ww);
                bool vx1 = (x1 >= 0) & (x1 < Ww);
                int y0c = min(max(y0, 0), Hh - 1);
                int y1c = min(max(y1, 0), Hh - 1);
                int x0c = min(max(x0, 0), Ww - 1);
                int x1c = min(max(x1, 0), Ww - 1);
                wgt[px][0] = (1.f - dy) * (1.f - dx) * (float)(vy0 && vx0);
                wgt[px][1] = (1.f - dy) * dx         * (float)(vy0 && vx1);
                wgt[px][2] = dy * (1.f - dx)         * (float)(vy1 && vx0);
                wgt[px][3] = dy * dx                 * (float)(vy1 && vx1);
                int ci[4] = {y0c * Ww + x0c, y0c * Ww + x1c,
                             y1c * Ww + x0c, y1c * Ww + x1c};
#pragma unroll
                for (int q = 0; q < 4; q++) {
                    const uint4* s = reinterpret_cast<const uint4*>(
                        xb + (size_t)ci[q] * 240);
                    uint4 t0 = s[0], t1 = s[1], t2 = s[2];
                    cdw[px][q][0] = t0.x; cdw[px][q][1] = t0.y;
                    cdw[px][q][2] = t0.z; cdw[px][q][3] = t0.w;
                    cdw[px][q][4] = t1.x; cdw[px][q][5] = t1.y;
                    cdw[px][q][6] = t1.z; cdw[px][q][7] = t1.w;
                    cdw[px][q][8] = t2.x; cdw[px][q][9] = t2.y;
                    cdw[px][q][10] = t2.z; cdw[px][q][11] = t2.w;
                }
            }
#pragma unroll
            for (int cp = 0; cp < 9; cp++) {
                float2 s0 = make_float2(0.f, 0.f);
                float2 s1 = make_float2(0.f, 0.f);
#pragma unroll
                for (int q = 0; q < 4; q++) {
                    uint32_t u0 = cdw[0][q][cp];
                    uint32_t u1 = cdw[1][q][cp];
                    float2 f0 = __half22float2(*reinterpret_cast<__half2*>(&u0));
                    float2 f1 = __half22float2(*reinterpret_cast<__half2*>(&u1));
                    s0.x += wgt[0][q] * f0.x; s0.y += wgt[0][q] * f0.y;
                    s1.x += wgt[1][q] * f1.x; s1.y += wgt[1][q] * f1.y;
                }
                *reinterpret_cast<__half2*>(&colb[(size_t)((2 * cp) * KK + kk) * HW]) =
                    __floats2half2_rn(s0.x, s1.x);
                *reinterpret_cast<__half2*>(&colb[(size_t)((2 * cp + 1) * KK + kk) * HW]) =
                    __floats2half2_rn(s0.y, s1.y);
            }
        }
    }
}

// ---------------- attention softmax (avg holds SUM over pixels) -------------
__global__ void attn_kernel(const float* __restrict__ avg,
                            const float* __restrict__ w_attn,
                            const float* __restrict__ b_attn,
                            float* __restrict__ attn)
{
    const int t = threadIdx.x;
    __shared__ float logits[4];
    if (t < 4) {
        int b = t >> 1, o = t & 1;
        float s = 0.f;
        for (int c = 0; c < CMID; c++)
            s += avg[b * CMID + c] * w_attn[o * CMID + c];
        logits[t] = b_attn[o] + s * (1.0f / HW);
    }
    __syncthreads();
    if (t < 2) {
        float l0 = logits[t * 2 + 0], l1 = logits[t * 2 + 1];
        float m = fmaxf(l0, l1);
        float e0 = expf(l0 - m), e1 = expf(l1 - m);
        float inv = 1.f / (e0 + e1);
        attn[t * 2 + 0] = e0 * inv;   // f_h weight
        attn[t * 2 + 1] = e1 * inv;   // f_w weight
    }
}

// ---------------- launcher ----------------
extern "C" void kernel_launch(void* const* d_in, const int* in_sizes, int n_in,
                              void* d_out, int out_size)
{
    const float* x        = (const float*)d_in[0];
    const float* w_reduce = (const float*)d_in[1];
    const float* b_reduce = (const float*)d_in[2];
    const float* w_offset = (const float*)d_in[3];
    const float* b_offset = (const float*)d_in[4];
    const float* w_dcnw   = (const float*)d_in[5];
    const float* b_dcnw   = (const float*)d_in[6];
    const float* w_dcnh   = (const float*)d_in[7];
    const float* b_dcnh   = (const float*)d_in[8];
    const float* w_expand = (const float*)d_in[9];
    const float* b_expand = (const float*)d_in[10];
    const float* w_attn   = (const float*)d_in[11];
    const float* b_attn   = (const float*)d_in[12];
    float* out = (float*)d_out;

    float *offs, *fw, *fh, *avg, *attn;
    cudaGetSymbolAddress((void**)&offs, g_offs);
    cudaGetSymbolAddress((void**)&fw,   g_fw);
    cudaGetSymbolAddress((void**)&fh,   g_fh);
    cudaGetSymbolAddress((void**)&avg,  g_avg);
    cudaGetSymbolAddress((void**)&attn, g_attn);
    __half *xp, *xrp, *xrt, *cw, *ch, *wpR, *wpO, *wpW, *wpH, *wpE;
    cudaGetSymbolAddress((void**)&xp,  g_xp);
    cudaGetSymbolAddress((void**)&xrp, g_xrp);
    cudaGetSymbolAddress((void**)&xrt, g_xrt);
    cudaGetSymbolAddress((void**)&cw,  g_cw);
    cudaGetSymbolAddress((void**)&ch,  g_ch);
    cudaGetSymbolAddress((void**)&wpR, g_wpR);
    cudaGetSymbolAddress((void**)&wpO, g_wpO);
    cudaGetSymbolAddress((void**)&wpW, g_wpW);
    cudaGetSymbolAddress((void**)&wpH, g_wpH);
    cudaGetSymbolAddress((void**)&wpE, g_wpE);

    constexpr int SM2 = 2 * 2 * 12800 + 2 * 8704;   // 68608
    constexpr int SM1 = 2 * 1 * 12800 + 2 * 8704;   // 43008
    cudaFuncSetAttribute((const void*)tgemm_kernel<2, false, true,  false, false>,
                         cudaFuncAttributeMaxDynamicSharedMemorySize, SM2);
    cudaFuncSetAttribute((const void*)tgemm_kernel<1, true,  false, false, false>,
                         cudaFuncAttributeMaxDynamicSharedMemorySize, SM1);
    cudaFuncSetAttribute((const void*)tgemm_kernel<1, true,  false, false, true>,
                         cudaFuncAttributeMaxDynamicSharedMemorySize, SM1);
    cudaFuncSetAttribute((const void*)tgemm_kernel<2, true,  false, true,  false>,
                         cudaFuncAttributeMaxDynamicSharedMemorySize, SM2);

    // 1) prep: weight prepacks + x->fp16 + avg zero
    prep_kernel<<<(PREP_TOTAL + 255) / 256, 256>>>(
        w_reduce, w_offset, w_dcnw, w_dcnh, w_expand, x,
        wpR, wpO, wpW, wpH, wpE, xp, avg);

    // 2) xr = reduce(x): 2-pass, emits only fp16 plane
    tgemm_kernel<2, false, true, false, false><<<dim3(72, 1, B), 256, SM2>>>(
        xp, (size_t)192 * HW, nullptr, nullptr, nullptr,
        wpR, 6, b_reduce, 180, nullptr, 0, xrp, FSTR, nullptr);

    // 3) transpose xrp -> xrt (pixel-major for gathers)
    transpose_kernel<<<dim3(HW / 64, B), 256>>>(xrp, xrt);

    // 4) offs = offset(xr): 1-pass
    tgemm_kernel<1, true, false, false, false><<<dim3(72, 2, B), 256, SM1>>>(
        xrp, FSTR, nullptr, nullptr, nullptr,
        wpO, 6, b_offset, 360, offs, OSTR, nullptr, 0, nullptr);

    // 5) im2col -> fp16 col planes (both convs)
    im2col_kernel<<<dim3(HW / 256, G, B), 128>>>(xrt, offs, cw, ch);

    // 6) deform GEMMs: 1-pass, fused mean accumulation
    tgemm_kernel<1, true, false, false, true><<<dim3(72, 1, B), 256, SM1>>>(
        cw, CSTR, nullptr, nullptr, nullptr,
        wpW, 51, b_dcnw, 180, fw, FSTR, nullptr, 0, avg);
    tgemm_kernel<1, true, false, false, true><<<dim3(72, 1, B), 256, SM1>>>(
        ch, CSTR, nullptr, nullptr, nullptr,
        wpH, 51, b_dcnh, 180, fh, FSTR, nullptr, 0, avg);

    // 7) attention
    attn_kernel<<<1, 64>>>(avg, w_attn, b_attn, attn);

    // 8) out = expand(attn0*f_h + attn1*f_w): 2-pass, mix fused
    tgemm_kernel<2, true, false, true, false><<<dim3(72, 1, B), 256, SM2>>>(
        nullptr, FSTR, fh, fw, attn,
        wpE, 6, b_expand, 192, out, (size_t)CIN * HW, nullptr, 0, nullptr);
}